// round 2
// baseline (speedup 1.0000x reference)
#include <cuda_runtime.h>
#include <float.h>

// ---------------------------------------------------------------------------
// Problem shape
// ---------------------------------------------------------------------------
#define M_Q   2048
#define N_P   32768
#define D_F   256
#define D2    512

// ---------------------------------------------------------------------------
// Spatial grid parameters
// ---------------------------------------------------------------------------
#define GSZ     64                  // cells per axis
#define NCELL   (GSZ*GSZ*GSZ)       // 262144
#define CS      1.5f                // cell size
#define INV_CS  (1.0f/1.5f)
#define BX      (-48.0f)            // grid origin (covers +-4.8 sigma)
#define CAP     32                  // bucket capacity per cell

#define F_INF __int_as_float(0x7f800000)

// ---------------------------------------------------------------------------
// Device scratch (static; no runtime allocation)
// ---------------------------------------------------------------------------
__device__ int    g_cnt[4][NCELL];          // per-cell point counts (atomic)
__device__ float4 g_bkt[4][NCELL][CAP];     // bucketed points (x,y,z,idx-bits)
__device__ float4 g_ovf[4][N_P];            // overflow points (rarely used)
__device__ int    g_ovfcnt[4];
__device__ int    g_idx[4][M_Q];            // NN result indices
__device__ float  g_partial[64][D_F];       // gather/max partials
// ---------------------------------------------------------------------------

// Kernel 0: zero the grid counters.
__global__ __launch_bounds__(256)
void zero_kernel()
{
    const int i = blockIdx.x * 256 + threadIdx.x;      // 0 .. 262143
    int4* p = (int4*)g_cnt;                            // 4*NCELL ints = 262144 int4
    p[i] = make_int4(0, 0, 0, 0);
    if (i < 4) g_ovfcnt[i] = 0;
}

// Kernel 1: scatter points into grid buckets (fused histogram + placement).
__global__ __launch_bounds__(256)
void build_kernel(const float* __restrict__ p0, const float* __restrict__ p1,
                  const float* __restrict__ p2, const float* __restrict__ p3)
{
    const int gid = blockIdx.x * 256 + threadIdx.x;    // 0 .. 131071
    const int s = gid >> 15;
    const int i = gid & (N_P - 1);
    const float* __restrict__ pos = (s == 0) ? p0 : (s == 1) ? p1 :
                                    (s == 2) ? p2 : p3;
    const float x = pos[i * 3 + 0];
    const float y = pos[i * 3 + 1];
    const float z = pos[i * 3 + 2];

    const int cx = min(max(__float2int_rd((x - BX) * INV_CS), 0), GSZ - 1);
    const int cy = min(max(__float2int_rd((y - BX) * INV_CS), 0), GSZ - 1);
    const int cz = min(max(__float2int_rd((z - BX) * INV_CS), 0), GSZ - 1);
    const int cell = (cz * GSZ + cy) * GSZ + cx;

    const float4 v = make_float4(x, y, z, __int_as_float(i));
    const int slot = atomicAdd(&g_cnt[s][cell], 1);
    if (slot < CAP) {
        g_bkt[s][cell][slot] = v;
    } else {
        const int o = atomicAdd(&g_ovfcnt[s], 1);      // always < N_P
        g_ovf[s][o] = v;
    }
}

// Kernel 2: exact NN via expanding Chebyshev rings. One warp per query.
__global__ __launch_bounds__(256)
void nn_query_kernel(const float* __restrict__ co, const float* __restrict__ cm)
{
    const int wgid = blockIdx.x * 8 + (threadIdx.x >> 5); // 0 .. 8191
    const int lane = threadIdx.x & 31;
    const int s  = wgid >> 11;                            // search 0..3
    const int qi = wgid & (M_Q - 1);

    const float* __restrict__ qb = (s < 2) ? co : cm;
    const float qx = qb[qi * 3 + 0];
    const float qy = qb[qi * 3 + 1];
    const float qz = qb[qi * 3 + 2];

    const int cx = min(max(__float2int_rd((qx - BX) * INV_CS), 0), GSZ - 1);
    const int cy = min(max(__float2int_rd((qy - BX) * INV_CS), 0), GSZ - 1);
    const int cz = min(max(__float2int_rd((qz - BX) * INV_CS), 0), GSZ - 1);

    float best = F_INF;
    int   bidx = 0x7fffffff;

    // Overflow points are not spatially indexed: scan them unconditionally.
    const int no = g_ovfcnt[s];
    for (int t = lane; t < no; t += 32) {
        const float4 p = g_ovf[s][t];
        const float ddx = p.x - qx, ddy = p.y - qy, ddz = p.z - qz;
        const float d2 = fmaf(ddx, ddx, fmaf(ddy, ddy, ddz * ddz));
        const int pi = __float_as_int(p.w);
        if (d2 < best || (d2 == best && pi < bidx)) { best = d2; bidx = pi; }
    }

    for (int r = 0; r <= GSZ; r++) {
        const int side = 2 * r + 1;
        const int nc2 = side * side;
        const int nc3 = nc2 * side;

        for (int base = 0; base < nc3; base += 32) {
            const int ci = base + lane;
            int cnt = 0;
            const float4* bp = nullptr;
            if (ci < nc3) {
                int dz = ci / nc2;
                int rem = ci - dz * nc2;
                int dy = rem / side;
                int dx = rem - dy * side;
                dx -= r; dy -= r; dz -= r;
                const int ch = max(abs(dx), max(abs(dy), abs(dz)));
                if (ch == r) {                      // ring surface only
                    const int x = cx + dx, y = cy + dy, z = cz + dz;
                    if ((unsigned)x < GSZ && (unsigned)y < GSZ && (unsigned)z < GSZ) {
                        const int cell = (z * GSZ + y) * GSZ + x;
                        cnt = min(g_cnt[s][cell], CAP);
                        bp = g_bkt[s][cell];
                    }
                }
            }
            for (int t = 0; t < cnt; t++) {
                const float4 p = bp[t];
                const float ddx = p.x - qx, ddy = p.y - qy, ddz = p.z - qz;
                const float d2 = fmaf(ddx, ddx, fmaf(ddy, ddy, ddz * ddz));
                const int pi = __float_as_int(p.w);
                if (d2 < best || (d2 == best && pi < bidx)) { best = d2; bidx = pi; }
            }
        }

        // warp-wide (min d2, min idx) butterfly reduce + broadcast
#pragma unroll
        for (int off = 16; off; off >>= 1) {
            const float ob = __shfl_xor_sync(0xffffffffu, best, off);
            const int   oi = __shfl_xor_sync(0xffffffffu, bidx, off);
            if (ob < best || (ob == best && oi < bidx)) { best = ob; bidx = oi; }
        }

        // Geometric guard: distance from q to the boundary of the fully
        // searched real-space box [cx-r, cx+r]^3. Faces at the grid edge are
        // "open" (all exterior points are clamp-binned into edge cells, which
        // are inside the box once it touches the edge).
        const float gxl = (cx - r <= 0)       ? F_INF : qx - (BX + (float)(cx - r) * CS);
        const float gxh = (cx + r >= GSZ - 1) ? F_INF : (BX + (float)(cx + r + 1) * CS) - qx;
        const float gyl = (cy - r <= 0)       ? F_INF : qy - (BX + (float)(cy - r) * CS);
        const float gyh = (cy + r >= GSZ - 1) ? F_INF : (BX + (float)(cy + r + 1) * CS) - qy;
        const float gzl = (cz - r <= 0)       ? F_INF : qz - (BX + (float)(cz - r) * CS);
        const float gzh = (cz + r >= GSZ - 1) ? F_INF : (BX + (float)(cz + r + 1) * CS) - qz;
        const float g = fminf(fminf(fminf(gxl, gxh), fminf(gyl, gyh)), fminf(gzl, gzh));

        if (best < g * g) break;   // strict: boundary-distance ties keep expanding
    }

    if (lane == 0) g_idx[s][qi] = bidx;
}

// Kernel 3: gather feature rows, average left/right, max-pool over 64-row chunk.
__global__ __launch_bounds__(256)
void gather_max_kernel(const float* __restrict__ f0, const float* __restrict__ f1,
                       const float* __restrict__ f2, const float* __restrict__ f3)
{
    const int side  = blockIdx.x >> 5;    // 0 = orig, 1 = mut
    const int chunk = blockIdx.x & 31;
    const int c     = threadIdx.x;

    const float* __restrict__ fa = side ? f2 : f0;
    const float* __restrict__ fb = side ? f3 : f1;
    const int* __restrict__ ia = g_idx[side ? 2 : 0];
    const int* __restrict__ ib = g_idx[side ? 3 : 1];

    __shared__ int sja[64], sjb[64];
    const int m0 = chunk * 64;
    if (threadIdx.x < 64)       sja[threadIdx.x]      = ia[m0 + threadIdx.x];
    else if (threadIdx.x < 128) sjb[threadIdx.x - 64] = ib[m0 + threadIdx.x - 64];
    __syncthreads();

    float mx = -FLT_MAX;
#pragma unroll 4
    for (int m = 0; m < 64; m++) {
        const float v = 0.5f * (fa[sja[m] * D_F + c] + fb[sjb[m] * D_F + c]);
        mx = fmaxf(mx, v);
    }
    g_partial[blockIdx.x][c] = mx;
}

// Kernel 4: finish max-pool -> x[512]; fc1 (relu) + fc2 fused in one block.
__global__ __launch_bounds__(512)
void fc_kernel(const float* __restrict__ w1, const float* __restrict__ b1,
               const float* __restrict__ w2, const float* __restrict__ b2,
               float* __restrict__ out)
{
    __shared__ float xs[D2];
    __shared__ float hs[D2];
    const int t = threadIdx.x;

    {   // global max over chunk partials
        const int side = t >> 8, cc = t & 255;
        float mx = -FLT_MAX;
#pragma unroll
        for (int k = 0; k < 32; k++)
            mx = fmaxf(mx, g_partial[side * 32 + k][cc]);
        xs[t] = mx;
    }
    __syncthreads();

    // fc1 row t: one thread per output, vectorized dot product
    const float4* __restrict__ wr4 = (const float4*)(w1 + (size_t)t * D2);
    const float4* __restrict__ xs4 = (const float4*)xs;
    float acc = 0.0f;
#pragma unroll 8
    for (int k = 0; k < D2 / 4; k++) {
        const float4 w = wr4[k];
        const float4 x = xs4[k];
        acc = fmaf(w.x, x.x, acc);
        acc = fmaf(w.y, x.y, acc);
        acc = fmaf(w.z, x.z, acc);
        acc = fmaf(w.w, x.w, acc);
    }
    const float h = fmaxf(acc + b1[t], 0.0f);
    hs[t] = h * w2[t];
    __syncthreads();

    // fc2: tree reduction over 512
#pragma unroll
    for (int s2 = 256; s2 > 0; s2 >>= 1) {
        if (t < s2) hs[t] += hs[t + s2];
        __syncthreads();
    }
    if (t == 0) out[0] = hs[0] + b2[0];
}

// ---------------------------------------------------------------------------
// Launch
// ---------------------------------------------------------------------------
extern "C" void kernel_launch(void* const* d_in, const int* in_sizes, int n_in,
                              void* d_out, int out_size)
{
    const float* co = (const float*)d_in[0];
    const float* cm = (const float*)d_in[1];
    const float* p0 = (const float*)d_in[2];
    const float* p1 = (const float*)d_in[3];
    const float* p2 = (const float*)d_in[4];
    const float* p3 = (const float*)d_in[5];
    const float* f0 = (const float*)d_in[6];
    const float* f1 = (const float*)d_in[7];
    const float* f2 = (const float*)d_in[8];
    const float* f3 = (const float*)d_in[9];
    const float* w1 = (const float*)d_in[10];
    const float* b1 = (const float*)d_in[11];
    const float* w2 = (const float*)d_in[12];
    const float* b2 = (const float*)d_in[13];
    float* out = (float*)d_out;

    zero_kernel<<<NCELL / 256, 256>>>();                 // 1024 blocks
    build_kernel<<<(4 * N_P) / 256, 256>>>(p0, p1, p2, p3);
    nn_query_kernel<<<(4 * M_Q) / 8, 256>>>(co, cm);     // warp per query
    gather_max_kernel<<<64, 256>>>(f0, f1, f2, f3);
    fc_kernel<<<1, 512>>>(w1, b1, w2, b2, out);
}

// round 3
// speedup vs baseline: 1.6463x; 1.6463x over previous
#include <cuda_runtime.h>
#include <float.h>

// ---------------------------------------------------------------------------
// Problem shape
// ---------------------------------------------------------------------------
#define M_Q   2048
#define N_P   32768
#define D_F   256
#define D2    512

#define NPART 4
#define PART  (N_P / NPART)      // 8192 points per partition
#define TILE  2048               // SMEM tile (32 KB SoA-paired)

typedef unsigned long long ull;

// ---------------------------------------------------------------------------
// Device scratch
// ---------------------------------------------------------------------------
__device__ float2       g_nn_part[4][M_Q][NPART];  // (d2, idx-bits) partials
__device__ unsigned int g_xmax[D2];                // order-encoded channel max

// ---------------------------------------------------------------------------
// Packed f32x2 helpers (Blackwell)
// ---------------------------------------------------------------------------
__device__ __forceinline__ ull fma2(ull a, ull b, ull c) {
    ull d;
    asm("fma.rn.f32x2 %0, %1, %2, %3;" : "=l"(d) : "l"(a), "l"(b), "l"(c));
    return d;
}
__device__ __forceinline__ ull pack2(float lo, float hi) {
    ull r;
    asm("mov.b64 %0, {%1, %2};" : "=l"(r) : "f"(lo), "f"(hi));
    return r;
}
__device__ __forceinline__ void unpack2(ull v, float& lo, float& hi) {
    asm("mov.b64 {%0, %1}, %2;" : "=f"(lo), "=f"(hi) : "l"(v));
}

// Order-preserving float<->uint encode for atomicMax over mixed-sign floats.
__device__ __forceinline__ unsigned int enc_f(float f) {
    unsigned int u = __float_as_uint(f);
    return (u & 0x80000000u) ? ~u : (u | 0x80000000u);
}
__device__ __forceinline__ float dec_f(unsigned int u) {
    return __uint_as_float((u & 0x80000000u) ? (u & 0x7FFFFFFFu) : ~u);
}

// ---------------------------------------------------------------------------
// Kernel 1: brute-force NN argmin, partitioned.
// argmin_p |q-p|^2 == argmin_p (|p|^2 - 2 q.p)
// Grid: 1024 blocks = 4 partitions x 4 searches x 64 query-blocks.
// Block: 256 thr = 8 warps, 4 queries/warp. SMEM tile SoA-paired for f32x2.
// ---------------------------------------------------------------------------
__global__ __launch_bounds__(256)
void nn_kernel(const float* __restrict__ co, const float* __restrict__ cm,
               const float* __restrict__ p0, const float* __restrict__ p1,
               const float* __restrict__ p2, const float* __restrict__ p3)
{
    const int bx     = blockIdx.x;
    const int part   = bx & 3;
    const int search = (bx >> 2) & 3;
    const int qblk   = bx >> 4;               // 0..63
    const int tid    = threadIdx.x;
    const int warp   = tid >> 5;
    const int lane   = tid & 31;

    // init the gather-stage max accumulator (runs before gather in stream order)
    if (bx < 2) g_xmax[bx * 256 + tid] = 0u;

    const float* __restrict__ q   = (search < 2) ? co : cm;
    const float* __restrict__ pos = (search == 0) ? p0 :
                                    (search == 1) ? p1 :
                                    (search == 2) ? p2 : p3;

    const int qbase = qblk * 32 + warp * 4;

    ull cx2[4], cy2[4], cz2[4];
    float best[4];
    int   bidx[4];
#pragma unroll
    for (int j = 0; j < 4; j++) {
        const int qi = qbase + j;
        const float nx = -2.0f * q[qi * 3 + 0];
        const float ny = -2.0f * q[qi * 3 + 1];
        const float nz = -2.0f * q[qi * 3 + 2];
        cx2[j] = pack2(nx, nx);
        cy2[j] = pack2(ny, ny);
        cz2[j] = pack2(nz, nz);
        best[j] = FLT_MAX;
        bidx[j] = 0;
    }

    // SoA-paired tile: ((float*)sx)[i] = x of candidate i; each ull = 2 cands.
    __shared__ ull sx[TILE / 2], sy[TILE / 2], sz[TILE / 2], sw[TILE / 2];

    const int pbase = part * PART;

    for (int t0 = 0; t0 < PART; t0 += TILE) {
        __syncthreads();
        for (int i = tid; i < TILE; i += 256) {
            const int gi = pbase + t0 + i;
            const float x = pos[gi * 3 + 0];
            const float y = pos[gi * 3 + 1];
            const float z = pos[gi * 3 + 2];
            ((float*)sx)[i] = x;
            ((float*)sy)[i] = y;
            ((float*)sz)[i] = z;
            ((float*)sw)[i] = fmaf(x, x, fmaf(y, y, z * z));
        }
        __syncthreads();

        const int gbase = pbase + t0;
#pragma unroll 2
        for (int k = lane; k < TILE / 2; k += 32) {
            const ull x2 = sx[k];
            const ull y2 = sy[k];
            const ull z2 = sz[k];
            const ull w2 = sw[k];
            const int i0 = gbase + 2 * k;
#pragma unroll
            for (int j = 0; j < 4; j++) {
                ull t2 = fma2(x2, cx2[j], w2);
                t2 = fma2(y2, cy2[j], t2);
                t2 = fma2(z2, cz2[j], t2);
                float lo, hi;
                unpack2(t2, lo, hi);
                if (lo < best[j]) { best[j] = lo; bidx[j] = i0; }
                if (hi < best[j]) { best[j] = hi; bidx[j] = i0 + 1; }
            }
        }
    }

    // warp-level (min d2, first index) reduction
#pragma unroll
    for (int off = 16; off; off >>= 1) {
#pragma unroll
        for (int j = 0; j < 4; j++) {
            const float ob = __shfl_down_sync(0xffffffffu, best[j], off);
            const int   oi = __shfl_down_sync(0xffffffffu, bidx[j], off);
            if (ob < best[j] || (ob == best[j] && oi < bidx[j])) {
                best[j] = ob; bidx[j] = oi;
            }
        }
    }
    if (lane == 0) {
#pragma unroll
        for (int j = 0; j < 4; j++)
            g_nn_part[search][qbase + j][part] =
                make_float2(best[j], __int_as_float(bidx[j]));
    }
}

// ---------------------------------------------------------------------------
// Kernel 2: reduce NN partials, gather feat rows, avg left/right, max-pool.
// Grid: 256 blocks = 2 sides x 128 chunks (16 rows each). 256 thr = channel.
// Channel max folded into deterministic integer atomicMax (order-encoded).
// ---------------------------------------------------------------------------
__global__ __launch_bounds__(256)
void gather_max_kernel(const float* __restrict__ f0, const float* __restrict__ f1,
                       const float* __restrict__ f2, const float* __restrict__ f3)
{
    const int side  = blockIdx.x >> 7;     // 0 = orig, 1 = mut
    const int chunk = blockIdx.x & 127;
    const int c     = threadIdx.x;
    const int m0    = chunk * 16;

    __shared__ int sj[2][16];
    if (threadIdx.x < 32) {
        const int which = threadIdx.x >> 4;           // 0 = left, 1 = right
        const int m = m0 + (threadIdx.x & 15);
        const int s = side * 2 + which;
        float2 p = g_nn_part[s][m][0];
        float bd = p.x;
        int   bi = __float_as_int(p.y);
#pragma unroll
        for (int pt = 1; pt < NPART; pt++) {
            const float2 r = g_nn_part[s][m][pt];
            const int ri = __float_as_int(r.y);
            if (r.x < bd || (r.x == bd && ri < bi)) { bd = r.x; bi = ri; }
        }
        sj[which][threadIdx.x & 15] = bi;
    }
    __syncthreads();

    const float* __restrict__ fa = side ? f2 : f0;
    const float* __restrict__ fb = side ? f3 : f1;

    float mx = -FLT_MAX;
#pragma unroll
    for (int m = 0; m < 16; m++) {
        const float v = 0.5f * (fa[(size_t)sj[0][m] * D_F + c] +
                                fb[(size_t)sj[1][m] * D_F + c]);
        mx = fmaxf(mx, v);
    }
    atomicMax(&g_xmax[side * 256 + c], enc_f(mx));
}

// ---------------------------------------------------------------------------
// Kernel 3: decode x[512]; fc1 (relu) + fc2 fused in one block.
// ---------------------------------------------------------------------------
__global__ __launch_bounds__(512)
void fc_kernel(const float* __restrict__ w1, const float* __restrict__ b1,
               const float* __restrict__ w2, const float* __restrict__ b2,
               float* __restrict__ out)
{
    __shared__ float xs[D2];
    __shared__ float hs[D2];
    const int t = threadIdx.x;

    xs[t] = dec_f(g_xmax[t]);
    __syncthreads();

    const float4* __restrict__ wr4 = (const float4*)(w1 + (size_t)t * D2);
    const float4* __restrict__ xs4 = (const float4*)xs;
    float acc = 0.0f;
#pragma unroll 8
    for (int k = 0; k < D2 / 4; k++) {
        const float4 w = wr4[k];
        const float4 x = xs4[k];
        acc = fmaf(w.x, x.x, acc);
        acc = fmaf(w.y, x.y, acc);
        acc = fmaf(w.z, x.z, acc);
        acc = fmaf(w.w, x.w, acc);
    }
    hs[t] = fmaxf(acc + b1[t], 0.0f) * w2[t];
    __syncthreads();

#pragma unroll
    for (int s2 = 256; s2 > 0; s2 >>= 1) {
        if (t < s2) hs[t] += hs[t + s2];
        __syncthreads();
    }
    if (t == 0) out[0] = hs[0] + b2[0];
}

// ---------------------------------------------------------------------------
// Launch
// ---------------------------------------------------------------------------
extern "C" void kernel_launch(void* const* d_in, const int* in_sizes, int n_in,
                              void* d_out, int out_size)
{
    const float* co = (const float*)d_in[0];
    const float* cm = (const float*)d_in[1];
    const float* p0 = (const float*)d_in[2];
    const float* p1 = (const float*)d_in[3];
    const float* p2 = (const float*)d_in[4];
    const float* p3 = (const float*)d_in[5];
    const float* f0 = (const float*)d_in[6];
    const float* f1 = (const float*)d_in[7];
    const float* f2 = (const float*)d_in[8];
    const float* f3 = (const float*)d_in[9];
    const float* w1 = (const float*)d_in[10];
    const float* b1 = (const float*)d_in[11];
    const float* w2 = (const float*)d_in[12];
    const float* b2 = (const float*)d_in[13];
    float* out = (float*)d_out;

    nn_kernel<<<NPART * 4 * (M_Q / 32), 256>>>(co, cm, p0, p1, p2, p3);
    gather_max_kernel<<<256, 256>>>(f0, f1, f2, f3);
    fc_kernel<<<1, 512>>>(w1, b1, w2, b2, out);
}